// round 13
// baseline (speedup 1.0000x reference)
#include <cuda_runtime.h>
#include <cuda_fp16.h>
#include <math.h>

#define PP 64
#define BB 2048
#define HH 128
#define NIN 2

constexpr long ENC_SZ = (long)BB * PP * HH;       // 16777216
constexpr long HN_SZ  = (long)PP * 2 * BB * HH;   // 33554432

constexpr int CHS        = 72;            // halfs per row in 64-k tiles (144B, ldsm conflict-free)
constexpr int TILE_H     = 128 * CHS;     // one 128x64 tile = 9216 halfs = 18432 B
constexpr int STG_STRIDE = 132;           // fp32 gate-staging stride (>=128!)

// smem layout (bytes): bias 512 | tileH1 2*18432 | tileX 2*18432 | Wring 2*18432
constexpr int SM_H1 = 512;
constexpr int SM_X  = SM_H1 + 2 * TILE_H * 2;
constexpr int SM_W  = SM_X + 2 * TILE_H * 2;
constexpr int SM_TOT = SM_W + 2 * TILE_H * 2;     // 111104

// fp16 permuted weights (static device scratch)
__device__ __half g_w0[512 * 128];                 // permuted Whh0
__device__ __half g_w1[512 * 256];                 // permuted [Wih1 | Whh1]

__device__ __forceinline__ float tanha(float x) {
    float y; asm("tanh.approx.f32 %0, %1;" : "=f"(y) : "f"(x)); return y;
}
__device__ __forceinline__ float sigf(float x) { return 0.5f * tanha(0.5f * x) + 0.5f; }

__device__ __forceinline__ unsigned sptr(const void* p) {
    return (unsigned)__cvta_generic_to_shared(p);
}
__device__ __forceinline__ void cp16(unsigned s, const void* g) {
    asm volatile("cp.async.cg.shared.global [%0], [%1], 16;\n" :: "r"(s), "l"(g));
}
__device__ __forceinline__ void cp_commit() {
    asm volatile("cp.async.commit_group;\n" ::: "memory");
}
__device__ __forceinline__ void ldsm4(unsigned& r0, unsigned& r1, unsigned& r2, unsigned& r3,
                                      const void* p) {
    asm volatile("ldmatrix.sync.aligned.m8n8.x4.shared.b16 {%0,%1,%2,%3}, [%4];\n"
                 : "=r"(r0), "=r"(r1), "=r"(r2), "=r"(r3)
                 : "r"(sptr(p)));
}

// ---- tiny pre-pass: permute W to fp16 (gate-interleaved columns) ----
__global__ __launch_bounds__(256) void prep_w(
    const float* __restrict__ Whh0,
    const float* __restrict__ Wih1,
    const float* __restrict__ Whh1)
{
    const long stride = (long)gridDim.x * blockDim.x;
    const long tid = (long)blockIdx.x * blockDim.x + threadIdx.x;
    for (long i = tid; i < 512 * 128; i += stride) {
        int pr = (int)(i >> 7), k = (int)(i & 127);
        int nb = pr >> 7, np = pr & 127;
        int norig = (np & 3) * 128 + nb * 32 + (np >> 2);
        g_w0[i] = __float2half_rn(Whh0[norig * 128 + k]);
    }
    for (long i = tid; i < 512 * 256; i += stride) {
        int pr = (int)(i >> 8), k = (int)(i & 255);
        int nb = pr >> 7, np = pr & 127;
        int norig = (np & 3) * 128 + nb * 32 + (np >> 2);
        float v = (k < 128) ? Wih1[norig * 128 + k] : Whh1[norig * 128 + (k - 128)];
        g_w1[i] = __float2half_rn(v);
    }
}

// Fused 2-layer LSTM: one CTA per 128-row m-block, 8 passes (L0 nb0..3, L1 nb0..3).
// A tiles resident in smem (h0 slices converted inline; h1 handed off in smem);
// W streamed in 64-k chunks through a ring-2 cp.async pipeline, drained at pass
// end so the epilogue (stride-132 staging, 2x64-row passes) reuses the W buffers.
__global__ __launch_bounds__(256, 2) void lstm_fused(
    const float* __restrict__ xin,
    const float* __restrict__ h0,
    const float* __restrict__ c0,
    const float* __restrict__ Wih0,
    const float* __restrict__ bih0,
    const float* __restrict__ bhh0,
    const float* __restrict__ bih1,
    const float* __restrict__ bhh1,
    float* __restrict__ dout)
{
    extern __shared__ __align__(16) unsigned char smem_raw[];
    float*  bsum   = (float*)smem_raw;
    __half* tileH1 = (__half*)(smem_raw + SM_H1);   // h1 (built by L0 epilogues)
    __half* tileX  = (__half*)(smem_raw + SM_X);    // h0-L0, later h0-L1
    __half* wring  = (__half*)(smem_raw + SM_W);    // 2 W chunk buffers

    const int tid  = threadIdx.x;
    const int lane = tid & 31;
    const int wid  = tid >> 5;
    const int grp  = lane >> 2;
    const int t4   = lane & 3;
    const int warpM = wid & 1;       // 2 warps along M: m64 each
    const int warpN = wid >> 1;      // 4 warps along N: n32 each

    const int mb = blockIdx.x;       // 1024 m-blocks of 128 rows
    const int p  = mb >> 4;
    const int b0 = (mb & 15) * 128;

    // ---- prologue: fill tileX with h0 layer-0 slice (fp32 -> fp16) ----
    {
        const float* src = h0 + ((long)(p * 2) * BB + b0) * HH;
        #pragma unroll
        for (int it = 0; it < 16; it++) {
            int idx = it * 256 + tid;            // 128 rows x 32 float4
            int row = idx >> 5, q = idx & 31;    // k = q*4 .. q*4+3
            float4 v = *(const float4*)(src + (long)row * HH + q * 4);
            __half* d = tileX + (q >> 4) * TILE_H + row * CHS + (q & 15) * 4;
            ((__half2*)d)[0] = __floats2half2_rn(v.x, v.y);
            ((__half2*)d)[1] = __floats2half2_rn(v.z, v.w);
        }
    }

    float* out_enc = dout;
    float* out_h   = dout + ENC_SZ;
    float* out_c   = dout + ENC_SZ + HN_SZ;

    float acc[4][4][4];

    for (int pass = 0; pass < 8; pass++) {
        const int layer = pass >> 2;
        const int nb    = pass & 3;
        const int NC    = layer ? 4 : 2;
        const int KT    = layer ? 256 : 128;
        const __half* gw = layer ? g_w1 : g_w0;

        // bias sums for this pass (safe: previous epilogue ended with a sync)
        if (tid < 128) {
            int g = tid & 3, u = tid >> 2, j = nb * 32 + u;
            bsum[tid] = layer ? (bih1[g * HH + j] + bhh1[g * HH + j])
                              : (bih0[g * HH + j] + bhh0[g * HH + j]);
        }

        #pragma unroll
        for (int i = 0; i < 4; i++)
            #pragma unroll
            for (int j = 0; j < 4; j++)
                #pragma unroll
                for (int k = 0; k < 4; k++) acc[i][j][k] = 0.f;

        auto load_w = [&](int c) {
            __half* buf = wring + (c & 1) * TILE_H;
            const int kkW = c * 64;
            #pragma unroll
            for (int it = 0; it < 4; it++) {
                int idx = it * 256 + tid;
                int np = idx >> 3, q = idx & 7;
                cp16(sptr(buf + np * CHS + q * 8),
                     gw + (long)(nb * 128 + np) * KT + kkW + q * 8);
            }
            cp_commit();
        };

        load_w(0);

        for (int c = 0; c < NC; c++) {
            if (c + 1 < NC) load_w(c + 1);
            if (c + 1 < NC) asm volatile("cp.async.wait_group 1;" ::: "memory");
            else            asm volatile("cp.async.wait_group 0;" ::: "memory");
            __syncthreads();

            // A sub-tile for this chunk (resident)
            const __half* Ab;
            if (layer == 0)   Ab = tileX  + c * TILE_H;
            else if (c < 2)   Ab = tileH1 + c * TILE_H;
            else              Ab = tileX  + (c - 2) * TILE_H;
            const __half* Wb = wring + (c & 1) * TILE_H;

            #pragma unroll
            for (int ks = 0; ks < 4; ks++) {
                const int kk = ks * 16;
                unsigned a[4][4];
                #pragma unroll
                for (int mt = 0; mt < 4; mt++) {
                    const int R = warpM * 64 + mt * 16;
                    const __half* pa = Ab + (R + (lane & 15)) * CHS + kk + ((lane >> 4) << 3);
                    ldsm4(a[mt][0], a[mt][1], a[mt][2], a[mt][3], pa);
                }
                unsigned b0r[4], b1r[4];
                {
                    const int C = warpN * 32;
                    const __half* pb0 = Wb + (C + lane) * CHS + kk;
                    ldsm4(b0r[0], b0r[1], b0r[2], b0r[3], pb0);
                    const __half* pb1 = Wb + (C + lane) * CHS + kk + 8;
                    ldsm4(b1r[0], b1r[1], b1r[2], b1r[3], pb1);
                }
                #pragma unroll
                for (int mt = 0; mt < 4; mt++) {
                    #pragma unroll
                    for (int nt = 0; nt < 4; nt++) {
                        asm volatile(
                            "mma.sync.aligned.m16n8k16.row.col.f32.f16.f16.f32 "
                            "{%0,%1,%2,%3}, {%4,%5,%6,%7}, {%8,%9}, {%0,%1,%2,%3};\n"
                            : "+f"(acc[mt][nt][0]), "+f"(acc[mt][nt][1]),
                              "+f"(acc[mt][nt][2]), "+f"(acc[mt][nt][3])
                            : "r"(a[mt][0]), "r"(a[mt][1]), "r"(a[mt][2]), "r"(a[mt][3]),
                              "r"(b0r[nt]), "r"(b1r[nt]));
                    }
                }
            }
            __syncthreads();   // W buf (c&1) reusable; all reads of this chunk done
        }

        // ---- epilogue: drained (wait_group 0 above). 2 passes of 64 rows,
        // staged at stride 132 across BOTH dead W buffers. ----
        float* sG = (float*)wring;   // 64*132*4 = 33792 B <= 36864 B

        #pragma unroll
        for (int half = 0; half < 2; half++) {
            if (warpM == half) {
                #pragma unroll
                for (int mt = 0; mt < 4; mt++) {
                    #pragma unroll
                    for (int nt = 0; nt < 4; nt++) {
                        int r   = mt * 16 + grp;
                        int col = warpN * 32 + nt * 8 + t4 * 2;
                        sG[r * STG_STRIDE + col]           = acc[mt][nt][0];
                        sG[r * STG_STRIDE + col + 1]       = acc[mt][nt][1];
                        sG[(r + 8) * STG_STRIDE + col]     = acc[mt][nt][2];
                        sG[(r + 8) * STG_STRIDE + col + 1] = acc[mt][nt][3];
                    }
                }
            }
            __syncthreads();

            #pragma unroll
            for (int it = 0; it < 8; it++) {
                int cell = it * 256 + tid;       // 64 rows x 32 units
                int ml = cell >> 5, jl = cell & 31;
                int row = half * 64 + ml;        // row within m-block
                int b = b0 + row;
                int j = nb * 32 + jl;

                const float4 g4 = *(const float4*)(sG + ml * STG_STRIDE + jl * 4);
                const float4 bs = *(const float4*)(bsum + jl * 4);
                float gi = g4.x + bs.x;
                float gf = g4.y + bs.y;
                float gg = g4.z + bs.z;
                float go = g4.w + bs.w;

                if (layer == 0) {
                    const float2 x2 = *(const float2*)(xin + ((long)b * PP + p) * NIN);
                    const float2 wi = *(const float2*)(Wih0 + (0 * HH + j) * NIN);
                    const float2 wf = *(const float2*)(Wih0 + (1 * HH + j) * NIN);
                    const float2 wg = *(const float2*)(Wih0 + (2 * HH + j) * NIN);
                    const float2 wo = *(const float2*)(Wih0 + (3 * HH + j) * NIN);
                    gi += x2.x * wi.x + x2.y * wi.y;
                    gf += x2.x * wf.x + x2.y * wf.y;
                    gg += x2.x * wg.x + x2.y * wg.y;
                    go += x2.x * wo.x + x2.y * wo.y;
                }

                const long sidx = ((long)(p * 2 + layer) * BB + b) * HH + j;
                const float cprev = c0[sidx];
                const float cn = sigf(gf) * cprev + sigf(gi) * tanha(gg);
                const float hn = sigf(go) * tanha(cn);

                out_h[sidx] = hn;
                out_c[sidx] = cn;
                if (layer == 0) {
                    // hand h1 off in smem, A-chunk format
                    tileH1[(j >> 6) * TILE_H + row * CHS + (j & 63)] = __float2half_rn(hn);
                } else {
                    out_enc[((long)b * PP + p) * HH + j] = hn;
                }
            }
            __syncthreads();
        }

        // after L0 completes, refill tileX with the h0 layer-1 slice
        if (pass == 3) {
            const float* src = h0 + ((long)(p * 2 + 1) * BB + b0) * HH;
            #pragma unroll
            for (int it = 0; it < 16; it++) {
                int idx = it * 256 + tid;
                int row = idx >> 5, q = idx & 31;
                float4 v = *(const float4*)(src + (long)row * HH + q * 4);
                __half* d = tileX + (q >> 4) * TILE_H + row * CHS + (q & 15) * 4;
                ((__half2*)d)[0] = __floats2half2_rn(v.x, v.y);
                ((__half2*)d)[1] = __floats2half2_rn(v.z, v.w);
            }
            __syncthreads();
        }
    }
}

extern "C" void kernel_launch(void* const* d_in, const int* in_sizes, int n_in,
                              void* d_out, int out_size)
{
    const float* xin  = (const float*)d_in[0];
    const float* h0   = (const float*)d_in[1];
    const float* c0   = (const float*)d_in[2];
    const float* Wih0 = (const float*)d_in[3];
    const float* Whh0 = (const float*)d_in[4];
    const float* bih0 = (const float*)d_in[5];
    const float* bhh0 = (const float*)d_in[6];
    const float* Wih1 = (const float*)d_in[7];
    const float* Whh1 = (const float*)d_in[8];
    const float* bih1 = (const float*)d_in[9];
    const float* bhh1 = (const float*)d_in[10];
    float* dout = (float*)d_out;

    cudaFuncSetAttribute(lstm_fused, cudaFuncAttributeMaxDynamicSharedMemorySize, SM_TOT);

    prep_w<<<256, 256>>>(Whh0, Wih1, Whh1);
    lstm_fused<<<1024, 256, SM_TOT>>>(xin, h0, c0, Wih0, bih0, bhh0, bih1, bhh1, dout);
}

// round 14
// speedup vs baseline: 1.1559x; 1.1559x over previous
#include <cuda_runtime.h>
#include <cuda_fp16.h>
#include <math.h>

#define PP 64
#define BB 2048
#define HH 128
#define NIN 2

constexpr long ENC_SZ = (long)BB * PP * HH;       // 16777216
constexpr long HN_SZ  = (long)PP * 2 * BB * HH;   // 33554432

constexpr int CHS        = 72;                 // halfs per row in chunk tiles (144B, ldsm conflict-free)
constexpr int TILE_H     = 128 * CHS;          // one chunk tile = 9216 halfs = 18432 B
constexpr int STG_STRIDE = 132;                // fp32 gate-staging stride (>=128!)

// fp16 scratch + flags (static device arrays -- allocation-free per harness rules)
__device__ __half g_h0h[(long)PP * 2 * BB * HH];   // h0 both layers, fp16
__device__ __half g_h1h[(long)PP * BB * HH];       // layer-0 output h1, fp16
__device__ __half g_w0[512 * 128];                 // permuted Whh0
__device__ __half g_w1[512 * 256];                 // permuted [Wih1 | Whh1]
__device__ int    g_flag[1024];                    // per-m-block L0-done counters

__device__ __forceinline__ float tanha(float x) {
    float y; asm("tanh.approx.f32 %0, %1;" : "=f"(y) : "f"(x)); return y;
}
__device__ __forceinline__ float sigf(float x) { return 0.5f * tanha(0.5f * x) + 0.5f; }

__device__ __forceinline__ unsigned sptr(const void* p) {
    return (unsigned)__cvta_generic_to_shared(p);
}
__device__ __forceinline__ void cp16(unsigned s, const void* g) {
    asm volatile("cp.async.cg.shared.global [%0], [%1], 16;\n" :: "r"(s), "l"(g));
}
__device__ __forceinline__ void cp_commit() {
    asm volatile("cp.async.commit_group;\n" ::: "memory");
}
__device__ __forceinline__ void ldsm4(unsigned& r0, unsigned& r1, unsigned& r2, unsigned& r3,
                                      const void* p) {
    asm volatile("ldmatrix.sync.aligned.m8n8.x4.shared.b16 {%0,%1,%2,%3}, [%4];\n"
                 : "=r"(r0), "=r"(r1), "=r"(r2), "=r"(r3)
                 : "r"(sptr(p)));
}

// ---- pre-pass: fp32 -> fp16 conversions (h0 full, W permuted) ----
__global__ __launch_bounds__(256) void prep(
    const float* __restrict__ h0,
    const float* __restrict__ Whh0,
    const float* __restrict__ Wih1,
    const float* __restrict__ Whh1)
{
    const long stride = (long)gridDim.x * blockDim.x;
    const long tid = (long)blockIdx.x * blockDim.x + threadIdx.x;

    const long n4 = (long)PP * 2 * BB * HH / 4;
    for (long i = tid; i < n4; i += stride) {
        float4 v = ((const float4*)h0)[i];
        ((__half2*)g_h0h)[2 * i]     = __floats2half2_rn(v.x, v.y);
        ((__half2*)g_h0h)[2 * i + 1] = __floats2half2_rn(v.z, v.w);
    }
    for (long i = tid; i < 512 * 128; i += stride) {
        int pr = (int)(i >> 7), k = (int)(i & 127);
        int nb = pr >> 7, np = pr & 127;
        int norig = (np & 3) * 128 + nb * 32 + (np >> 2);
        g_w0[i] = __float2half_rn(Whh0[norig * 128 + k]);
    }
    for (long i = tid; i < 512 * 256; i += stride) {
        int pr = (int)(i >> 8), k = (int)(i & 255);
        int nb = pr >> 7, np = pr & 127;
        int norig = (np & 3) * 128 + nb * 32 + (np >> 2);
        float v = (k < 128) ? Wih1[norig * 128 + k] : Whh1[norig * 128 + (k - 128)];
        g_w1[i] = __float2half_rn(v);
    }
}

// One layer pass: R7's proven mainloop (K=64 A+W chunks, ring-2, m64xn32
// warp tiles, fp16 m16n8k16) with single-barrier-per-chunk scheduling and
// the R7 epilogue (stride-132 staging into the dead ring).
// LAYER==1 chunk order: h0-L1 chunks first, h1 chunks last (flag-gated).
template <int LAYER>
__device__ __forceinline__ void lstm_pass(
    const int tid, const int lane, const int warpM, const int warpN,
    const int grp, const int t4, const int nb, const int p, const int b0,
    const int mb,
    __half* chunks, float* bsum,
    const float* __restrict__ xin,
    const float* __restrict__ c0,
    const float* __restrict__ Wih0,
    const float* __restrict__ bih0, const float* __restrict__ bhh0,
    const float* __restrict__ bih1, const float* __restrict__ bhh1,
    float* __restrict__ dout)
{
    constexpr int NC = LAYER ? 4 : 2;
    const __half* gw = LAYER ? g_w1 : g_w0;
    constexpr int KT = LAYER ? 256 : 128;

    if (tid < 128) {
        int g = tid & 3, u = tid >> 2, j = nb * 32 + u;
        bsum[tid] = LAYER ? (bih1[g * HH + j] + bhh1[g * HH + j])
                          : (bih0[g * HH + j] + bhh0[g * HH + j]);
    }

    float acc[4][4][4];
    #pragma unroll
    for (int i = 0; i < 4; i++)
        #pragma unroll
        for (int j = 0; j < 4; j++)
            #pragma unroll
            for (int k = 0; k < 4; k++) acc[i][j][k] = 0.f;

    auto load_chunk = [&](int c) {
        const __half* Ah;
        int kkA, kkW;
        if (LAYER == 0) {
            Ah = g_h0h + ((long)(p * 2) * BB + b0) * HH;      kkA = c * 64;  kkW = c * 64;
        } else if (c < 2) {   // h0-L1 against Whh1 (ready immediately)
            Ah = g_h0h + ((long)(p * 2 + 1) * BB + b0) * HH;  kkA = c * 64;  kkW = 128 + c * 64;
        } else {              // h1 against Wih1 (flag-gated)
            Ah = g_h1h + ((long)p * BB + b0) * HH;            kkA = (c - 2) * 64; kkW = (c - 2) * 64;
        }
        __half* buf = chunks + (c & 1) * 2 * TILE_H;
        #pragma unroll
        for (int it = 0; it < 4; it++) {
            int idx = it * 256 + tid;
            int row = idx >> 3, q = idx & 7;
            cp16(sptr(buf + row * CHS + q * 8), Ah + (long)row * HH + kkA + q * 8);
        }
        #pragma unroll
        for (int it = 0; it < 4; it++) {
            int idx = it * 256 + tid;
            int np = idx >> 3, q = idx & 7;
            cp16(sptr(buf + TILE_H + np * CHS + q * 8),
                 gw + (long)(nb * 128 + np) * KT + kkW + q * 8);
        }
        cp_commit();
    };

    load_chunk(0);

    for (int c = 0; c < NC; c++) {
        asm volatile("cp.async.wait_group 0;" ::: "memory");
        __syncthreads();     // chunk c visible; all reads of buf[(c+1)&1] (iter c-1) done
        if (LAYER == 1 && c == 1) {
            // gate the h1 chunk loads on all 4 sibling CTAs' L0 completion
            if (tid == 0) {
                while (atomicAdd(&g_flag[mb], 0) < 4) __nanosleep(64);
            }
            __syncthreads();
            __threadfence();
        }
        if (c + 1 < NC) load_chunk(c + 1);

        const __half* Ab = chunks + (c & 1) * 2 * TILE_H;
        const __half* Wb = Ab + TILE_H;

        #pragma unroll
        for (int ks = 0; ks < 4; ks++) {
            const int kk = ks * 16;
            unsigned a[4][4];
            #pragma unroll
            for (int mt = 0; mt < 4; mt++) {
                const int R = warpM * 64 + mt * 16;
                const __half* pa = Ab + (R + (lane & 15)) * CHS + kk + ((lane >> 4) << 3);
                ldsm4(a[mt][0], a[mt][1], a[mt][2], a[mt][3], pa);
            }
            unsigned b0r[4], b1r[4];
            {
                const int C = warpN * 32;
                const __half* pb0 = Wb + (C + lane) * CHS + kk;
                ldsm4(b0r[0], b0r[1], b0r[2], b0r[3], pb0);
                const __half* pb1 = Wb + (C + lane) * CHS + kk + 8;
                ldsm4(b1r[0], b1r[1], b1r[2], b1r[3], pb1);
            }
            #pragma unroll
            for (int mt = 0; mt < 4; mt++) {
                #pragma unroll
                for (int nt = 0; nt < 4; nt++) {
                    asm volatile(
                        "mma.sync.aligned.m16n8k16.row.col.f32.f16.f16.f32 "
                        "{%0,%1,%2,%3}, {%4,%5,%6,%7}, {%8,%9}, {%0,%1,%2,%3};\n"
                        : "+f"(acc[mt][nt][0]), "+f"(acc[mt][nt][1]),
                          "+f"(acc[mt][nt][2]), "+f"(acc[mt][nt][3])
                        : "r"(a[mt][0]), "r"(a[mt][1]), "r"(a[mt][2]), "r"(a[mt][3]),
                          "r"(b0r[nt]), "r"(b1r[nt]));
                }
            }
        }
    }
    __syncthreads();   // final chunk's reads done before staging overwrites ring

    // ---- stage gates (fp32) into the dead chunk buffers, stride 132 ----
    float* sG = (float*)chunks;     // 128*132*4 = 67584 B <= 73728 B of ring
    #pragma unroll
    for (int mt = 0; mt < 4; mt++) {
        #pragma unroll
        for (int nt = 0; nt < 4; nt++) {
            int r   = warpM * 64 + mt * 16 + grp;
            int col = warpN * 32 + nt * 8 + t4 * 2;
            sG[r * STG_STRIDE + col]           = acc[mt][nt][0];
            sG[r * STG_STRIDE + col + 1]       = acc[mt][nt][1];
            sG[(r + 8) * STG_STRIDE + col]     = acc[mt][nt][2];
            sG[(r + 8) * STG_STRIDE + col + 1] = acc[mt][nt][3];
        }
    }
    __syncthreads();

    // ---- fused LSTM cell epilogue ----
    float* out_enc = dout;
    float* out_h   = dout + ENC_SZ;
    float* out_c   = dout + ENC_SZ + HN_SZ;

    #pragma unroll
    for (int it = 0; it < 16; it++) {
        int cell = it * 256 + tid;        // 128 rows x 32 units
        int ml = cell >> 5, jl = cell & 31;
        int b = b0 + ml;
        int j = nb * 32 + jl;

        const float4 g4 = *(const float4*)(sG + ml * STG_STRIDE + jl * 4);
        const float4 bs = *(const float4*)(bsum + jl * 4);
        float gi = g4.x + bs.x;
        float gf = g4.y + bs.y;
        float gg = g4.z + bs.z;
        float go = g4.w + bs.w;

        if (LAYER == 0) {
            const float2 x2 = *(const float2*)(xin + ((long)b * PP + p) * NIN);
            const float2 wi = *(const float2*)(Wih0 + (0 * HH + j) * NIN);
            const float2 wf = *(const float2*)(Wih0 + (1 * HH + j) * NIN);
            const float2 wg = *(const float2*)(Wih0 + (2 * HH + j) * NIN);
            const float2 wo = *(const float2*)(Wih0 + (3 * HH + j) * NIN);
            gi += x2.x * wi.x + x2.y * wi.y;
            gf += x2.x * wf.x + x2.y * wf.y;
            gg += x2.x * wg.x + x2.y * wg.y;
            go += x2.x * wo.x + x2.y * wo.y;
        }

        const long sidx = ((long)(p * 2 + LAYER) * BB + b) * HH + j;
        const float cprev = c0[sidx];
        const float cn = sigf(gf) * cprev + sigf(gi) * tanha(gg);
        const float hn = sigf(go) * tanha(cn);

        out_h[sidx] = hn;
        out_c[sidx] = cn;
        if (LAYER == 0) {
            g_h1h[((long)p * BB + b) * HH + j] = __float2half_rn(hn);
        } else {
            out_enc[((long)b * PP + p) * HH + j] = hn;
        }
    }

    if (LAYER == 0) {
        __threadfence();            // h1 stores visible before flag
        __syncthreads();            // all threads' stores issued+fenced
        if (tid == 0) atomicAdd(&g_flag[mb], 1);
    } else {
        __syncthreads();            // keep ring/bsum safe for any caller reuse
    }
    if (LAYER == 0) __syncthreads();    // bsum/ring safe before next pass writes
}

// Fused 2-layer kernel: every CTA runs L0 for its (nb, mb), publishes h1 +
// flag, then runs L1 (h0-L1 chunks first; h1 chunks gated on sibling flags).
__global__ __launch_bounds__(256, 2) void lstm_fused(
    const float* __restrict__ xin,
    const float* __restrict__ c0,
    const float* __restrict__ Wih0,
    const float* __restrict__ bih0,
    const float* __restrict__ bhh0,
    const float* __restrict__ bih1,
    const float* __restrict__ bhh1,
    float* __restrict__ dout)
{
    extern __shared__ __align__(16) unsigned char smem_raw[];
    float*  bsum   = (float*)smem_raw;                    // 128 permuted bias sums
    __half* chunks = (__half*)(smem_raw + 512);           // 2 buf x (A tile + W tile)

    const int tid  = threadIdx.x;
    const int lane = tid & 31;
    const int wid  = tid >> 5;
    const int grp  = lane >> 2;
    const int t4   = lane & 3;
    const int warpM = wid & 1;
    const int warpN = wid >> 1;

    const int nb = blockIdx.x;       // units [nb*32, nb*32+32)
    const int mb = blockIdx.y;       // 1024 m-blocks of 128 rows
    const int p  = mb >> 4;
    const int b0 = (mb & 15) * 128;

    lstm_pass<0>(tid, lane, warpM, warpN, grp, t4, nb, p, b0, mb,
                 chunks, bsum, xin, c0, Wih0, bih0, bhh0, bih1, bhh1, dout);
    lstm_pass<1>(tid, lane, warpM, warpN, grp, t4, nb, p, b0, mb,
                 chunks, bsum, xin, c0, Wih0, bih0, bhh0, bih1, bhh1, dout);
}

extern "C" void kernel_launch(void* const* d_in, const int* in_sizes, int n_in,
                              void* d_out, int out_size)
{
    const float* xin  = (const float*)d_in[0];
    const float* h0   = (const float*)d_in[1];
    const float* c0   = (const float*)d_in[2];
    const float* Wih0 = (const float*)d_in[3];
    const float* Whh0 = (const float*)d_in[4];
    const float* bih0 = (const float*)d_in[5];
    const float* bhh0 = (const float*)d_in[6];
    const float* Wih1 = (const float*)d_in[7];
    const float* Whh1 = (const float*)d_in[8];
    const float* bih1 = (const float*)d_in[9];
    const float* bhh1 = (const float*)d_in[10];
    float* dout = (float*)d_out;

    // reset per-m-block flags every launch (graph-captured memset node)
    void* flag_ptr = nullptr;
    cudaGetSymbolAddress(&flag_ptr, g_flag);
    cudaMemsetAsync(flag_ptr, 0, 1024 * sizeof(int));

    const int smem_bytes = 512 + 4 * TILE_H * (int)sizeof(__half);   // 74240 -> 2 CTAs/SM
    cudaFuncSetAttribute(lstm_fused, cudaFuncAttributeMaxDynamicSharedMemorySize, smem_bytes);

    prep<<<1024, 256>>>(h0, Whh0, Wih1, Whh1);
    lstm_fused<<<dim3(4, 1024), 256, smem_bytes>>>(xin, c0, Wih0, bih0, bhh0,
                                                   bih1, bhh1, dout);
}